// round 6
// baseline (speedup 1.0000x reference)
#include <cuda_runtime.h>
#include <math.h>

// ---------------- scratch (__device__ globals; no allocations) ----------------
__device__ float g_x0 [4*16*32*32];
__device__ float g_xa [4*4*64*64];
__device__ float g_xb [4*4*128*128];
__device__ float g_xc [4*4*256*256];
__device__ float g_g64 [4*3*64*64];
__device__ float g_g128[4*3*128*128];
__device__ float g_g256[4*3*256*256];

// ============================================================================
// PREP: 1x1 conv (384->16)+leaky fused with all 3 guide resizes.
// Half-pixel integer-ratio bilinear => exact 0.25 * 2x2 box.
// ============================================================================
__device__ __forceinline__ void resize_scalar(
    const float* __restrict__ g, float* __restrict__ out, int OH, int f, int idx)
{
    if (idx >= 4*3*OH*OH) return;
    int ow = idx % OH;
    int t  = idx / OH;
    int oh = t % OH;
    int pl = t / OH;
    const float* gp = g + pl*512*512;
    const float* r0 = gp + (f*oh + (f>>1) - 1)*512 + (f*ow + (f>>1) - 1);
    out[idx] = 0.25f*(r0[0] + r0[1] + r0[512] + r0[513]);
}

__global__ __launch_bounds__(256) void prep_kernel(
    const float* __restrict__ x, const float* __restrict__ lw,
    const float* __restrict__ lb, const float* __restrict__ guide,
    float* __restrict__ x0,
    float* __restrict__ o256, float* __restrict__ o128, float* __restrict__ o64)
{
    const int bid = blockIdx.x;
    const int tid = threadIdx.x;

    if (bid < 64) {
        __shared__ float sw[16*384];
        for (int i = tid; i < 16*384; i += 256) sw[i] = lw[i];
        __syncthreads();
        const int pix = bid*64 + (tid & 63);
        const int b   = pix >> 10;
        const int hw  = pix & 1023;
        const int o0  = (tid >> 6) * 4;
        const float* xp  = x + b*384*1024 + hw;
        const float* w0p = sw + (o0+0)*384;
        const float* w1p = sw + (o0+1)*384;
        const float* w2p = sw + (o0+2)*384;
        const float* w3p = sw + (o0+3)*384;
        float a0=0.f, a1=0.f, a2=0.f, a3=0.f;
        #pragma unroll 4
        for (int i = 0; i < 384; ++i) {
            float xv = xp[i*1024];
            a0 += w0p[i]*xv; a1 += w1p[i]*xv; a2 += w2p[i]*xv; a3 += w3p[i]*xv;
        }
        a0 += lb[o0+0]; a1 += lb[o0+1]; a2 += lb[o0+2]; a3 += lb[o0+3];
        a0 = (a0 >= 0.f) ? a0 : 0.01f*a0;
        a1 = (a1 >= 0.f) ? a1 : 0.01f*a1;
        a2 = (a2 >= 0.f) ? a2 : 0.01f*a2;
        a3 = (a3 >= 0.f) ? a3 : 0.01f*a3;
        float* op = x0 + (b*16 + o0)*1024 + hw;
        op[0] = a0; op[1024] = a1; op[2048] = a2; op[3072] = a3;
    } else if (bid < 832) {
        int idx = (bid - 64)*256 + tid;
        int ow4 = idx & 63;
        int t   = idx >> 6;
        int oh  = t & 255;
        int pl  = t >> 8;
        const float* gp = guide + pl*512*512 + (2*oh)*512 + ow4*8;
        float4 a = ((const float4*)gp)[0];
        float4 b4 = ((const float4*)gp)[1];
        float4 c = ((const float4*)(gp + 512))[0];
        float4 d = ((const float4*)(gp + 512))[1];
        float4 r;
        r.x = 0.25f*(a.x + a.y + c.x + c.y);
        r.y = 0.25f*(a.z + a.w + c.z + c.w);
        r.z = 0.25f*(b4.x + b4.y + d.x + d.y);
        r.w = 0.25f*(b4.z + b4.w + d.z + d.w);
        ((float4*)o256)[idx] = r;
    } else if (bid < 1600) {
        resize_scalar(guide, o128, 128, 4, (bid - 832)*256 + tid);
    } else {
        resize_scalar(guide, o64,   64, 8, (bid - 1600)*256 + tid);
    }
}

// ============================================================================
// Tiled PAC conv fused with up2_nearest. float4 smem tiles, sentinel OOB.
// Block = 32x16 outputs; each thread computes TWO outputs (rows ty, ty+8)
// for doubled ILP. ACT: 1 = leaky, 2 = sigmoid.
// ============================================================================
#define TW 32
#define TH 16
#define GP (TW+2)            // 34
#define GTILE ((TH+2)*GP)    // 612
#define XP (TW/2+2)          // 18
#define XTILE ((TH/2+2)*XP)  // 180

template<int CI, int CO, int ACT>
__global__ __launch_bounds__(256) void pac_tile(
    const float* __restrict__ xin,   // (4,CI,H/2,W/2)
    const float* __restrict__ gd,    // (4,3,H,W)
    const float* __restrict__ wt,    // (CO,CI,3,3)
    float* __restrict__ out,         // (4,CO,H,W)
    int H, int W)
{
    constexpr int NC4 = CI/4;
    __shared__ float4 sg[GTILE];             // guide: {g0,g1,g2,_}
    __shared__ float4 sx[XTILE*NC4];         // x: NC4 float4 per half-res pixel
    __shared__ float4 swt[9*CO*NC4];         // weights k-major

    const int tid = threadIdx.x;
    const int b   = blockIdx.z;
    const int h0  = blockIdx.y * TH;
    const int w0  = blockIdx.x * TW;
    const int HW  = H*W;
    const int H2 = H >> 1, W2 = W >> 1, HW2 = H2*W2;

    // ---- stage guide tile (sentinel 1e19 outside image -> kern == 0) ----
    const float* gb = gd + b*3*HW;
    for (int i = tid; i < GTILE; i += 256) {
        int r = i / GP, q = i - r*GP;
        int gh = h0 - 1 + r, gw = w0 - 1 + q;
        float4 v;
        if ((gh >= 0) & (gh < H) & (gw >= 0) & (gw < W)) {
            int off = gh*W + gw;
            v.x = gb[off]; v.y = gb[HW + off]; v.z = gb[2*HW + off];
        } else {
            v.x = v.y = v.z = 1e19f;
        }
        v.w = 0.f;
        sg[i] = v;
    }
    // ---- stage x tile (half-res, zero halo) ----
    const float* xb = xin + b*CI*HW2;
    for (int i = tid; i < XTILE*NC4; i += 256) {
        int pos = i / NC4, c4 = i - pos*NC4;
        int r = pos / XP, q = pos - r*XP;
        int xh = (h0>>1) - 1 + r, xw = (w0>>1) - 1 + q;
        float4 v = make_float4(0.f, 0.f, 0.f, 0.f);
        if ((xh >= 0) & (xh < H2) & (xw >= 0) & (xw < W2)) {
            int off = xh*W2 + xw;
            const float* p = xb + (c4*4)*HW2 + off;
            v.x = p[0]; v.y = p[HW2]; v.z = p[2*HW2]; v.w = p[3*HW2];
        }
        sx[i] = v;
    }
    // ---- weights: regs for CO==1, smem k-major otherwise ----
    float4 wr[CO == 1 ? 9*NC4 : 1];
    if (CO == 1) {
        #pragma unroll
        for (int k = 0; k < 9; ++k)
            #pragma unroll
            for (int c4 = 0; c4 < NC4; ++c4) {
                float4 v;
                v.x = __ldg(wt + (c4*4 + 0)*9 + k);
                v.y = __ldg(wt + (c4*4 + 1)*9 + k);
                v.z = __ldg(wt + (c4*4 + 2)*9 + k);
                v.w = __ldg(wt + (c4*4 + 3)*9 + k);
                wr[k*NC4 + c4] = v;
            }
    } else {
        for (int i = tid; i < 9*CO*NC4; i += 256) {
            int c4 = i % NC4;
            int t2 = i / NC4;
            int o  = t2 % CO;
            int k  = t2 / CO;
            float4 v;
            v.x = wt[(o*CI + c4*4 + 0)*9 + k];
            v.y = wt[(o*CI + c4*4 + 1)*9 + k];
            v.z = wt[(o*CI + c4*4 + 2)*9 + k];
            v.w = wt[(o*CI + c4*4 + 3)*9 + k];
            swt[i] = v;
        }
    }
    __syncthreads();

    const int ty = tid >> 5, tx = tid & 31;      // pixel A: (ty, tx); pixel B: (ty+8, tx)
    const int giA = (ty+1)*GP + (tx+1);
    const int giB = giA + 8*GP;
    const float4 gcA = sg[giA];
    const float4 gcB = sg[giB];

    float accA[CO], accB[CO];
    #pragma unroll
    for (int o = 0; o < CO; ++o) { accA[o] = 0.f; accB[o] = 0.f; }

    #pragma unroll
    for (int k = 0; k < 9; ++k) {
        const int di = k/3 - 1, dj = k%3 - 1;
        float4 gA = sg[giA + di*GP + dj];
        float4 gB = sg[giB + di*GP + dj];
        float dA0 = gA.x - gcA.x, dA1 = gA.y - gcA.y, dA2 = gA.z - gcA.z;
        float dB0 = gB.x - gcB.x, dB1 = gB.y - gcB.y, dB2 = gB.z - gcB.z;
        float kernA = __expf(-0.5f*(dA0*dA0 + dA1*dA1 + dA2*dA2));
        float kernB = __expf(-0.5f*(dB0*dB0 + dB1*dB1 + dB2*dB2));

        const int xoA = ((((ty+di)>>1)+1)*XP + (((tx+dj)>>1)+1)) * NC4;
        const int xoB = xoA + 4*XP*NC4;        // (ty+8+di)>>1 == ((ty+di)>>1)+4
        #pragma unroll
        for (int o = 0; o < CO; ++o) {
            float sA = 0.f, sB = 0.f;
            #pragma unroll
            for (int c4 = 0; c4 < NC4; ++c4) {
                float4 wv = (CO == 1) ? wr[k*NC4 + c4] : swt[(k*CO + o)*NC4 + c4];
                float4 xA = sx[xoA + c4];
                float4 xB = sx[xoB + c4];
                sA += wv.x*xA.x + wv.y*xA.y + wv.z*xA.z + wv.w*xA.w;
                sB += wv.x*xB.x + wv.y*xB.y + wv.z*xB.z + wv.w*xB.w;
            }
            accA[o] += kernA * sA;
            accB[o] += kernB * sB;
        }
    }

    const int hA = h0 + ty, hB = hA + 8, w = w0 + tx;
    #pragma unroll
    for (int o = 0; o < CO; ++o) {
        float vA = accA[o], vB = accB[o];
        if (ACT == 1) {
            vA = (vA >= 0.f) ? vA : 0.01f*vA;
            vB = (vB >= 0.f) ? vB : 0.01f*vB;
        } else {
            vA = 1.0f / (1.0f + __expf(-vA));
            vB = 1.0f / (1.0f + __expf(-vB));
        }
        out[(b*CO + o)*HW + hA*W + w] = vA;
        out[(b*CO + o)*HW + hB*W + w] = vB;
    }
}

// ---------------- launch ----------------
extern "C" void kernel_launch(void* const* d_in, const int* in_sizes, int n_in,
                              void* d_out, int out_size)
{
    const float* x     = (const float*)d_in[0];
    const float* guide = (const float*)d_in[1];
    const float* lin_w = (const float*)d_in[2];
    const float* lin_b = (const float*)d_in[3];
    const float* w0    = (const float*)d_in[4];
    const float* w1    = (const float*)d_in[5];
    const float* w2    = (const float*)d_in[6];
    const float* w3    = (const float*)d_in[7];
    float* out = (float*)d_out;

    float *x0, *xa, *xb, *xc, *gg64, *gg128, *gg256;
    cudaGetSymbolAddress((void**)&x0,    g_x0);
    cudaGetSymbolAddress((void**)&xa,    g_xa);
    cudaGetSymbolAddress((void**)&xb,    g_xb);
    cudaGetSymbolAddress((void**)&xc,    g_xc);
    cudaGetSymbolAddress((void**)&gg64,  g_g64);
    cudaGetSymbolAddress((void**)&gg128, g_g128);
    cudaGetSymbolAddress((void**)&gg256, g_g256);

    prep_kernel<<<1792, 256>>>(x, lin_w, lin_b, guide, x0, gg256, gg128, gg64);

    pac_tile<16,4,1><<<dim3( 2,  4, 4), 256>>>(x0, gg64,  w0, xa,  64,  64);
    pac_tile< 4,4,1><<<dim3( 4,  8, 4), 256>>>(xa, gg128, w1, xb, 128, 128);
    pac_tile< 4,4,1><<<dim3( 8, 16, 4), 256>>>(xb, gg256, w2, xc, 256, 256);
    pac_tile< 4,1,2><<<dim3(16, 32, 4), 256>>>(xc, guide, w3, out, 512, 512);
}

// round 7
// speedup vs baseline: 1.5696x; 1.5696x over previous
#include <cuda_runtime.h>
#include <math.h>

// ---------------- scratch (__device__ globals; no allocations) ----------------
__device__ float g_x0 [4*16*32*32];
__device__ float g_xa [4*4*64*64];
__device__ float g_xb [4*4*128*128];
__device__ float g_xc [4*4*256*256];
__device__ float g_g64 [4*3*64*64];
__device__ float g_g128[4*3*128*128];
__device__ float g_g256[4*3*256*256];

// ============================================================================
// PREP: 1x1 conv (384->16)+leaky fused with all 3 guide resizes.
// ============================================================================
__device__ __forceinline__ void resize_scalar(
    const float* __restrict__ g, float* __restrict__ out, int OH, int f, int idx)
{
    if (idx >= 4*3*OH*OH) return;
    int ow = idx % OH;
    int t  = idx / OH;
    int oh = t % OH;
    int pl = t / OH;
    const float* gp = g + pl*512*512;
    const float* r0 = gp + (f*oh + (f>>1) - 1)*512 + (f*ow + (f>>1) - 1);
    out[idx] = 0.25f*(r0[0] + r0[1] + r0[512] + r0[513]);
}

__global__ __launch_bounds__(256) void prep_kernel(
    const float* __restrict__ x, const float* __restrict__ lw,
    const float* __restrict__ lb, const float* __restrict__ guide,
    float* __restrict__ x0,
    float* __restrict__ o256, float* __restrict__ o128, float* __restrict__ o64)
{
    const int bid = blockIdx.x;
    const int tid = threadIdx.x;

    if (bid < 64) {
        __shared__ float sw[16*384];
        for (int i = tid; i < 16*384; i += 256) sw[i] = lw[i];
        __syncthreads();
        const int pix = bid*64 + (tid & 63);
        const int b   = pix >> 10;
        const int hw  = pix & 1023;
        const int o0  = (tid >> 6) * 4;
        const float* xp  = x + b*384*1024 + hw;
        const float* w0p = sw + (o0+0)*384;
        const float* w1p = sw + (o0+1)*384;
        const float* w2p = sw + (o0+2)*384;
        const float* w3p = sw + (o0+3)*384;
        float a0=0.f, a1=0.f, a2=0.f, a3=0.f;
        #pragma unroll 4
        for (int i = 0; i < 384; ++i) {
            float xv = xp[i*1024];
            a0 += w0p[i]*xv; a1 += w1p[i]*xv; a2 += w2p[i]*xv; a3 += w3p[i]*xv;
        }
        a0 += lb[o0+0]; a1 += lb[o0+1]; a2 += lb[o0+2]; a3 += lb[o0+3];
        a0 = (a0 >= 0.f) ? a0 : 0.01f*a0;
        a1 = (a1 >= 0.f) ? a1 : 0.01f*a1;
        a2 = (a2 >= 0.f) ? a2 : 0.01f*a2;
        a3 = (a3 >= 0.f) ? a3 : 0.01f*a3;
        float* op = x0 + (b*16 + o0)*1024 + hw;
        op[0] = a0; op[1024] = a1; op[2048] = a2; op[3072] = a3;
    } else if (bid < 832) {
        int idx = (bid - 64)*256 + tid;
        int ow4 = idx & 63;
        int t   = idx >> 6;
        int oh  = t & 255;
        int pl  = t >> 8;
        const float* gp = guide + pl*512*512 + (2*oh)*512 + ow4*8;
        float4 a = ((const float4*)gp)[0];
        float4 b4 = ((const float4*)gp)[1];
        float4 c = ((const float4*)(gp + 512))[0];
        float4 d = ((const float4*)(gp + 512))[1];
        float4 r;
        r.x = 0.25f*(a.x + a.y + c.x + c.y);
        r.y = 0.25f*(a.z + a.w + c.z + c.w);
        r.z = 0.25f*(b4.x + b4.y + d.x + d.y);
        r.w = 0.25f*(b4.z + b4.w + d.z + d.w);
        ((float4*)o256)[idx] = r;
    } else if (bid < 1600) {
        resize_scalar(guide, o128, 128, 4, (bid - 832)*256 + tid);
    } else {
        resize_scalar(guide, o64,   64, 8, (bid - 1600)*256 + tid);
    }
}

// ============================================================================
// pac_tile: CI=16 stage only (64x64, small). Same as R3 best.
// ============================================================================
#define TW 32
#define TH 8
#define GP (TW+2)
#define GTILE ((TH+2)*GP)
#define XP (TW/2+2)
#define XTILE ((TH/2+2)*XP)

template<int CI, int CO>
__global__ __launch_bounds__(256) void pac_tile(
    const float* __restrict__ xin, const float* __restrict__ gd,
    const float* __restrict__ wt, float* __restrict__ out,
    int H, int W)
{
    constexpr int NC4 = CI/4;
    __shared__ float4 sg[GTILE];
    __shared__ float4 sx[XTILE*NC4];
    __shared__ float4 swt[9*CO*NC4];

    const int tid = threadIdx.x;
    const int b   = blockIdx.z;
    const int h0  = blockIdx.y * TH;
    const int w0  = blockIdx.x * TW;
    const int HW  = H*W;
    const int H2 = H >> 1, W2 = W >> 1, HW2 = H2*W2;

    const float* gb = gd + b*3*HW;
    for (int i = tid; i < GTILE; i += 256) {
        int r = i / GP, q = i - r*GP;
        int gh = h0 - 1 + r, gw = w0 - 1 + q;
        float4 v;
        if ((gh >= 0) & (gh < H) & (gw >= 0) & (gw < W)) {
            int off = gh*W + gw;
            v.x = gb[off]; v.y = gb[HW + off]; v.z = gb[2*HW + off];
        } else { v.x = v.y = v.z = 1e19f; }
        v.w = 0.f;
        sg[i] = v;
    }
    const float* xb = xin + b*CI*HW2;
    for (int i = tid; i < XTILE*NC4; i += 256) {
        int pos = i / NC4, c4 = i - pos*NC4;
        int r = pos / XP, q = pos - r*XP;
        int xh = (h0>>1) - 1 + r, xw = (w0>>1) - 1 + q;
        float4 v = make_float4(0.f, 0.f, 0.f, 0.f);
        if ((xh >= 0) & (xh < H2) & (xw >= 0) & (xw < W2)) {
            int off = xh*W2 + xw;
            const float* p = xb + (c4*4)*HW2 + off;
            v.x = p[0]; v.y = p[HW2]; v.z = p[2*HW2]; v.w = p[3*HW2];
        }
        sx[i] = v;
    }
    for (int i = tid; i < 9*CO*NC4; i += 256) {
        int c4 = i % NC4;
        int t2 = i / NC4;
        int o  = t2 % CO;
        int k  = t2 / CO;
        float4 v;
        v.x = wt[(o*CI + c4*4 + 0)*9 + k];
        v.y = wt[(o*CI + c4*4 + 1)*9 + k];
        v.z = wt[(o*CI + c4*4 + 2)*9 + k];
        v.w = wt[(o*CI + c4*4 + 3)*9 + k];
        swt[i] = v;
    }
    __syncthreads();

    const int ty = tid >> 5, tx = tid & 31;
    const int gi0 = (ty+1)*GP + (tx+1);
    const float4 gc = sg[gi0];

    float acc[CO];
    #pragma unroll
    for (int o = 0; o < CO; ++o) acc[o] = 0.f;

    #pragma unroll
    for (int k = 0; k < 9; ++k) {
        const int di = k/3 - 1, dj = k%3 - 1;
        float4 g4 = sg[gi0 + di*GP + dj];
        float d0 = g4.x - gc.x, d1 = g4.y - gc.y, d2 = g4.z - gc.z;
        float kern = __expf(-0.5f*(d0*d0 + d1*d1 + d2*d2));
        const int xo = ((((ty+di)>>1)+1)*XP + (((tx+dj)>>1)+1)) * NC4;
        #pragma unroll
        for (int o = 0; o < CO; ++o) {
            float s = 0.f;
            #pragma unroll
            for (int c4 = 0; c4 < NC4; ++c4) {
                float4 xv = sx[xo + c4];
                float4 wv = swt[(k*CO + o)*NC4 + c4];
                s += wv.x*xv.x + wv.y*xv.y + wv.z*xv.z + wv.w*xv.w;
            }
            acc[o] += kern * s;
        }
    }
    const int h = h0 + ty, w = w0 + tx;
    #pragma unroll
    for (int o = 0; o < CO; ++o) {
        float v = acc[o];
        v = (v >= 0.f) ? v : 0.01f*v;
        out[(b*CO + o)*HW + h*W + w] = v;
    }
}

// ============================================================================
// pac_quad: CI=4 stages. Thread computes a 2x2 output quad.
// x window (3x3 float4) in registers; weights o-vectorized in smem (CO=4)
// or registers (CO=1); guide halo in smem with OOB sentinel.
// Tile 32x32 outputs, 256 threads (16x16 quads). ACT: 1 leaky, 2 sigmoid.
// ============================================================================
#define QT 32                 // tile edge (outputs)
#define QGP (QT+2)            // 34
#define QGT (QGP*QGP)         // 1156
#define QXP (QT/2+2)          // 18
#define QXT (QXP*QXP)         // 324

template<int CO, int ACT>
__global__ __launch_bounds__(256) void pac_quad(
    const float* __restrict__ xin,   // (4,4,H/2,W/2)
    const float* __restrict__ gd,    // (4,3,H,W)
    const float* __restrict__ wt,    // (CO,4,3,3)
    float* __restrict__ out,         // (4,CO,H,W)
    int H, int W)
{
    __shared__ float4 sg[QGT];
    __shared__ float4 sx[QXT];
    __shared__ float4 swt[9*4];      // [k][ci] -> float4 over o (CO=4 only)

    const int tid = threadIdx.x;
    const int b   = blockIdx.z;
    const int h0  = blockIdx.y * QT;
    const int w0  = blockIdx.x * QT;
    const int HW  = H*W;
    const int H2 = H >> 1, W2 = W >> 1, HW2 = H2*W2;

    // ---- stage guide halo (sentinel OOB) ----
    const float* gb = gd + b*3*HW;
    for (int i = tid; i < QGT; i += 256) {
        int r = i / QGP, q = i - r*QGP;
        int gh = h0 - 1 + r, gw = w0 - 1 + q;
        float4 v;
        if ((gh >= 0) & (gh < H) & (gw >= 0) & (gw < W)) {
            int off = gh*W + gw;
            v.x = gb[off]; v.y = gb[HW + off]; v.z = gb[2*HW + off];
        } else { v.x = v.y = v.z = 1e19f; }
        v.w = 0.f;
        sg[i] = v;
    }
    // ---- stage x halo (half-res, zero pad) ----
    const float* xb = xin + b*4*HW2;
    for (int i = tid; i < QXT; i += 256) {
        int r = i / QXP, q = i - r*QXP;
        int xh = (h0>>1) - 1 + r, xw = (w0>>1) - 1 + q;
        float4 v = make_float4(0.f, 0.f, 0.f, 0.f);
        if ((xh >= 0) & (xh < H2) & (xw >= 0) & (xw < W2)) {
            int off = xh*W2 + xw;
            const float* p = xb + off;
            v.x = p[0]; v.y = p[HW2]; v.z = p[2*HW2]; v.w = p[3*HW2];
        }
        sx[i] = v;
    }
    // ---- weights ----
    float4 wr[CO == 1 ? 9 : 1];
    if (CO == 1) {
        #pragma unroll
        for (int k = 0; k < 9; ++k) {
            float4 v;
            v.x = __ldg(wt + 0*9 + k);
            v.y = __ldg(wt + 1*9 + k);
            v.z = __ldg(wt + 2*9 + k);
            v.w = __ldg(wt + 3*9 + k);
            wr[k] = v;
        }
    } else {
        if (tid < 36) {
            int ci = tid & 3, k = tid >> 2;
            float4 v;
            v.x = wt[(0*4 + ci)*9 + k];
            v.y = wt[(1*4 + ci)*9 + k];
            v.z = wt[(2*4 + ci)*9 + k];
            v.w = wt[(3*4 + ci)*9 + k];
            swt[k*4 + ci] = v;
        }
    }
    __syncthreads();

    const int qy = tid >> 4, qx = tid & 15;

    // ---- x window into registers: 3x3 float4 ----
    float4 xw[9];
    #pragma unroll
    for (int rr = 0; rr < 3; ++rr)
        #pragma unroll
        for (int cc = 0; cc < 3; ++cc)
            xw[rr*3+cc] = sx[(qy+rr)*QXP + (qx+cc)];

    // ---- guide centers ----
    const int gbase = (2*qy+1)*QGP + (2*qx+1);
    float4 gq[4];
    gq[0] = sg[gbase];
    gq[1] = sg[gbase + 1];
    gq[2] = sg[gbase + QGP];
    gq[3] = sg[gbase + QGP + 1];

    float4 acc4[4];
    float  acc1[4];
    #pragma unroll
    for (int p = 0; p < 4; ++p) {
        acc4[p] = make_float4(0.f,0.f,0.f,0.f);
        acc1[p] = 0.f;
    }

    #pragma unroll
    for (int k = 0; k < 9; ++k) {
        const int di = k/3 - 1, dj = k%3 - 1;
        float4 wv0, wv1, wv2, wv3;
        if (CO == 4) {
            wv0 = swt[k*4+0]; wv1 = swt[k*4+1]; wv2 = swt[k*4+2]; wv3 = swt[k*4+3];
        }
        #pragma unroll
        for (int p = 0; p < 4; ++p) {
            const int rr = p >> 1, cc = p & 1;
            float4 g4 = sg[gbase + (rr+di)*QGP + (cc+dj)];
            float d0 = g4.x - gq[p].x, d1 = g4.y - gq[p].y, d2 = g4.z - gq[p].z;
            float kern = __expf(-0.5f*(d0*d0 + d1*d1 + d2*d2));
            // half-res window index (compile-time after unroll)
            const int xr = (rr + di + 2) >> 1;   // 0..2
            const int xc = (cc + dj + 2) >> 1;
            float4 xv = xw[xr*3 + xc];
            if (CO == 4) {
                acc4[p].x += kern*(xv.x*wv0.x + xv.y*wv1.x + xv.z*wv2.x + xv.w*wv3.x);
                acc4[p].y += kern*(xv.x*wv0.y + xv.y*wv1.y + xv.z*wv2.y + xv.w*wv3.y);
                acc4[p].z += kern*(xv.x*wv0.z + xv.y*wv1.z + xv.z*wv2.z + xv.w*wv3.z);
                acc4[p].w += kern*(xv.x*wv0.w + xv.y*wv1.w + xv.z*wv2.w + xv.w*wv3.w);
            } else {
                float4 wv = wr[k];
                acc1[p] += kern*(xv.x*wv.x + xv.y*wv.y + xv.z*wv.z + xv.w*wv.w);
            }
        }
    }

    const int h = h0 + 2*qy, w = w0 + 2*qx;
    if (CO == 4) {
        #pragma unroll
        for (int p = 0; p < 4; ++p) {
            float4 v = acc4[p];
            v.x = (v.x >= 0.f) ? v.x : 0.01f*v.x;
            v.y = (v.y >= 0.f) ? v.y : 0.01f*v.y;
            v.z = (v.z >= 0.f) ? v.z : 0.01f*v.z;
            v.w = (v.w >= 0.f) ? v.w : 0.01f*v.w;
            acc4[p] = v;
        }
        float* op = out + b*4*HW + h*W + w;
        *(float2*)(op)            = make_float2(acc4[0].x, acc4[1].x);
        *(float2*)(op + W)        = make_float2(acc4[2].x, acc4[3].x);
        op += HW;
        *(float2*)(op)            = make_float2(acc4[0].y, acc4[1].y);
        *(float2*)(op + W)        = make_float2(acc4[2].y, acc4[3].y);
        op += HW;
        *(float2*)(op)            = make_float2(acc4[0].z, acc4[1].z);
        *(float2*)(op + W)        = make_float2(acc4[2].z, acc4[3].z);
        op += HW;
        *(float2*)(op)            = make_float2(acc4[0].w, acc4[1].w);
        *(float2*)(op + W)        = make_float2(acc4[2].w, acc4[3].w);
    } else {
        #pragma unroll
        for (int p = 0; p < 4; ++p) {
            if (ACT == 1) acc1[p] = (acc1[p] >= 0.f) ? acc1[p] : 0.01f*acc1[p];
            else          acc1[p] = 1.0f / (1.0f + __expf(-acc1[p]));
        }
        float* op = out + b*HW + h*W + w;
        *(float2*)(op)     = make_float2(acc1[0], acc1[1]);
        *(float2*)(op + W) = make_float2(acc1[2], acc1[3]);
    }
}

// ---------------- launch ----------------
extern "C" void kernel_launch(void* const* d_in, const int* in_sizes, int n_in,
                              void* d_out, int out_size)
{
    const float* x     = (const float*)d_in[0];
    const float* guide = (const float*)d_in[1];
    const float* lin_w = (const float*)d_in[2];
    const float* lin_b = (const float*)d_in[3];
    const float* w0    = (const float*)d_in[4];
    const float* w1    = (const float*)d_in[5];
    const float* w2    = (const float*)d_in[6];
    const float* w3    = (const float*)d_in[7];
    float* out = (float*)d_out;

    float *x0, *xa, *xb, *xc, *gg64, *gg128, *gg256;
    cudaGetSymbolAddress((void**)&x0,    g_x0);
    cudaGetSymbolAddress((void**)&xa,    g_xa);
    cudaGetSymbolAddress((void**)&xb,    g_xb);
    cudaGetSymbolAddress((void**)&xc,    g_xc);
    cudaGetSymbolAddress((void**)&gg64,  g_g64);
    cudaGetSymbolAddress((void**)&gg128, g_g128);
    cudaGetSymbolAddress((void**)&gg256, g_g256);

    prep_kernel<<<1792, 256>>>(x, lin_w, lin_b, guide, x0, gg256, gg128, gg64);

    pac_tile<16,4><<<dim3( 2,  8, 4), 256>>>(x0, gg64,  w0, xa,  64,  64);
    pac_quad<4,1><<<dim3( 4,  4, 4), 256>>>(xa, gg128, w1, xb, 128, 128);
    pac_quad<4,1><<<dim3( 8,  8, 4), 256>>>(xb, gg256, w2, xc, 256, 256);
    pac_quad<1,2><<<dim3(16, 16, 4), 256>>>(xc, guide, w3, out, 512, 512);
}